// round 13
// baseline (speedup 1.0000x reference)
// FSAS_V5 fused forward — one CTA per 8x8 patch, 512 threads.
// R13: serialization diet — restructured chunk loop (W-STS overlaps dw conv,
// -2 barriers), dw weights in registers via LDG (no smem round-trip),
// B-fragments via single ldsm4 (hi+lo in one op), w_proj STS inside phase 4.
#include <cuda_runtime.h>
#include <cuda_bf16.h>
#include <cstdint>

#define HH 256
#define WW 256
#define EPSF 1e-6f
#define L2T_OVER_32 0.41524101186092030f

// ---- dynamic smem layout (float offsets) ----
#define OFF_QKV  0                 // 384 * 65 fp32
#define OFF_HID  24960             // 128 * 101 fp32 hidden chunk
#define OFF_CORR OFF_HID           // 128 * 65 overlay (phase 4+)
#define OFF_G    37888             // g_norm[128], g_qnorm[128], g_knorm[128]
#define OFF_SC   38272             // sincos: cos[512], sin[512]
#define OFF_RQ   40448
#define OFF_RK   40512
#define OFF_RN   40576
#define ARENA_F  40640             // bf16 tile arena @ byte 162,560
// phase-1 arena (rows strided 144 B -> ldmatrix conflict-free)
#define XHI 0
#define XLO 14976
#define WHI 29952
#define WLO 48384
// proj arena (rows strided 272 B) — SAME bytes as phase-1 arena, reused later
#define WPH 0
#define WPL 17408
#define CBH 34816
#define CBL 52224
#define ARENA_BYTES 69632
#define SMEM_BYTES (ARENA_F * 4 + ARENA_BYTES)   // 232,192 B

// ---- prepacked weights (constant across CTAs) ----
__device__ uint32_t g_whi[3][128 * 36];   // w_hidden hi, rows 144 B
__device__ uint32_t g_wlo[3][128 * 36];   // w_hidden lo
__device__ uint32_t g_wph[64 * 68];       // w_proj hi, rows 272 B
__device__ uint32_t g_wpl[64 * 68];       // w_proj lo

__device__ __forceinline__ uint32_t smem_u32(const void* p) {
    uint32_t a;
    asm("{ .reg .u64 t; cvta.to.shared.u64 t, %1; cvt.u32.u64 %0, t; }"
        : "=r"(a) : "l"(p));
    return a;
}
__device__ __forceinline__ void ldsm4(uint32_t* r, uint32_t addr) {
    asm volatile("ldmatrix.sync.aligned.m8n8.x4.shared.b16 {%0,%1,%2,%3}, [%4];"
                 : "=r"(r[0]), "=r"(r[1]), "=r"(r[2]), "=r"(r[3]) : "r"(addr));
}
__device__ __forceinline__ void mma16816(float* c, const uint32_t* a,
                                         uint32_t b0, uint32_t b1) {
    asm volatile("mma.sync.aligned.m16n8k16.row.col.f32.bf16.bf16.f32 "
                 "{%0,%1,%2,%3}, {%4,%5,%6,%7}, {%8,%9}, {%0,%1,%2,%3};"
                 : "+f"(c[0]), "+f"(c[1]), "+f"(c[2]), "+f"(c[3])
                 : "r"(a[0]), "r"(a[1]), "r"(a[2]), "r"(a[3]), "r"(b0), "r"(b1));
}
__device__ __forceinline__ uint32_t pack_hi_lo(float v0, float v1, uint32_t& lo) {
    __nv_bfloat16 h0 = __float2bfloat16(v0);
    __nv_bfloat16 h1 = __float2bfloat16(v1);
    __nv_bfloat16 l0 = __float2bfloat16(v0 - __bfloat162float(h0));
    __nv_bfloat16 l1 = __float2bfloat16(v1 - __bfloat162float(h1));
    lo = ((uint32_t)__bfloat16_as_ushort(l1) << 16) | __bfloat16_as_ushort(l0);
    return ((uint32_t)__bfloat16_as_ushort(h1) << 16) | __bfloat16_as_ushort(h0);
}
// ---- packed f32x2 helpers ----
__device__ __forceinline__ uint64_t pk2(float lo, float hi) {
    uint64_t r; asm("mov.b64 %0, {%1, %2};" : "=l"(r) : "f"(lo), "f"(hi)); return r;
}
__device__ __forceinline__ void upk2(float& lo, float& hi, uint64_t v) {
    asm("mov.b64 {%0, %1}, %2;" : "=f"(lo), "=f"(hi) : "l"(v));
}
__device__ __forceinline__ void fma2(uint64_t& d, uint64_t a, uint64_t b) {
    asm("fma.rn.f32x2 %0, %1, %2, %0;" : "+l"(d) : "l"(a), "l"(b));
}

// circ conv body, i-parity P compile-time (see R9).
template<int P>
__device__ __forceinline__ void circ_par(const float* qb, const float* kb,
                                         int A0, float* outv)
{
    uint64_t krp[4][8];
    #pragma unroll
    for (int t = 0; t < 4; ++t) {
        #pragma unroll
        for (int c = 0; c < 8; ++c) {
            int r0 = (2*t + P + A0) & 7;
            int r1 = (2*t + P + 1 + A0) & 7;
            krp[t][c] = pk2(kb[r0*8 + c], kb[r1*8 + c]);
        }
    }
    uint64_t acc2[2][8];
    #pragma unroll
    for (int rp = 0; rp < 2; ++rp)
        #pragma unroll
        for (int bb = 0; bb < 8; ++bb) acc2[rp][bb] = pk2(0.f, 0.f);
    #pragma unroll
    for (int ii = 0; ii < 4; ++ii) {
        const int i = P + 2*ii;
        #pragma unroll
        for (int j = 0; j < 8; ++j) {
            float qs = qb[i*8 + j];
            uint64_t qq = pk2(qs, qs);
            #pragma unroll
            for (int rp = 0; rp < 2; ++rp) {
                const int t = (rp - P - ii) & 3;
                #pragma unroll
                for (int bb = 0; bb < 8; ++bb)
                    fma2(acc2[rp][bb], qq, krp[t][(bb - j) & 7]);
            }
        }
    }
    #pragma unroll
    for (int rp = 0; rp < 2; ++rp)
        #pragma unroll
        for (int bb = 0; bb < 8; ++bb)
            upk2(outv[(2*rp)*8 + bb], outv[(2*rp+1)*8 + bb], acc2[rp][bb]);
}

// ---- prep kernel: pack constant weights into arena layout ----
__global__ void prep_weights(const float* __restrict__ w_hidden,
                             const float* __restrict__ w_proj)
{
    int t = blockIdx.x * blockDim.x + threadIdx.x;
    if (t < 3 * 128 * 32) {
        int c = t >> 12, rem = t & 4095, r = rem >> 5, cp = rem & 31;
        float2 wv = ((const float2*)w_hidden)[(c * 128 + r) * 32 + cp];
        uint32_t lp, hp = pack_hi_lo(wv.x, wv.y, lp);
        g_whi[c][r * 36 + cp] = hp;
        g_wlo[c][r * 36 + cp] = lp;
    } else if (t < 3 * 128 * 32 + 64 * 64) {
        int i = t - 3 * 128 * 32;
        int o = i >> 6, kp = i & 63;
        float2 wv = ((const float2*)w_proj)[o * 64 + kp];
        uint32_t lp, hp = pack_hi_lo(wv.x, wv.y, lp);
        g_wph[o * 68 + kp] = hp;
        g_wpl[o * 68 + kp] = lp;
    }
}

__global__ __launch_bounds__(512, 1)
void fsas_fused_kernel(const float* __restrict__ x,
                       const float* __restrict__ w_dw,
                       const float* __restrict__ g_norm,
                       const float* __restrict__ g_qnorm,
                       const float* __restrict__ g_knorm,
                       float* __restrict__ out)
{
    extern __shared__ float sm[];
    const int tid  = threadIdx.x;
    const int lane = tid & 31;
    const int warp = tid >> 5;
    const int px = blockIdx.x, py = blockIdx.y, b = blockIdx.z;
    const int gx0 = px * 8, gy0 = py * 8;

    char* smc = (char*)sm;
    const uint32_t sbase = smem_u32(sm);
    const uint32_t arena = sbase + ARENA_F * 4;

    // ---- prefetch chunk 0 W (prepacked uint4) ----
    uint4 wph4[2], wpl4[2];
    #pragma unroll
    for (int t = 0; t < 2; ++t) {
        int w4 = tid + t * 512;
        int row = w4 >> 3, colw = (w4 & 7) * 4;
        wph4[t] = *(const uint4*)&g_whi[0][row * 36 + colw];
        wpl4[t] = *(const uint4*)&g_wlo[0][row * 36 + colw];
    }
    // dw weights chunk 0 -> regs (per-thread channel)
    const int dwch = tid & 127;
    float dwv[9];
    #pragma unroll
    for (int t = 0; t < 9; ++t)
        dwv[t] = __ldg(w_dw + dwch * 9 + t);

    // ---- phase 0: x halo (coalesced) -> bf16 hi/lo Xt tiles; sincos; g ----
    const float* xb = x + (size_t)b * 64 * HH * WW;
    for (int it = warp; it < 104; it += 16) {
        int cpBase = it / 13;
        int posBase = it - cpBase * 13;
        int cp  = cpBase * 4 + (lane >> 3);
        int pos = posBase * 8 + (lane & 7);
        float x0 = 0.f, x1 = 0.f;
        if (pos < 100) {
            int Y = pos / 10, X = pos - Y * 10;
            int gy = gy0 - 1 + Y, gx = gx0 - 1 + X;
            if ((unsigned)gy < HH && (unsigned)gx < WW) {
                size_t base = (size_t)(2 * cp) * (HH * WW) + gy * WW + gx;
                x0 = __ldg(xb + base);
                x1 = __ldg(xb + base + (size_t)(HH * WW));
            }
        }
        uint32_t lp, hp = pack_hi_lo(x0, x1, lp);
        uint32_t off = (uint32_t)(pos * 144 + cp * 4);
        *(uint32_t*)(smc + ARENA_F * 4 + XHI + off) = hp;
        *(uint32_t*)(smc + ARENA_F * 4 + XLO + off) = lp;
    }
    {   // sincos table
        int flag = tid >> 8, mm = (tid >> 3) & 31, d = tid & 7;
        float pos = (float)((flag ? gx0 : gy0) + d);
        float inv = exp2f(-L2T_OVER_32 * (float)mm);
        float sn, cs;
        sincosf(pos * inv, &sn, &cs);
        sm[OFF_SC + flag * 256 + mm * 8 + d]       = cs;
        sm[OFF_SC + 512 + flag * 256 + mm * 8 + d] = sn;
    }
    if (tid < 384) {
        float v = (tid < 128) ? __ldg(g_norm + tid)
                : (tid < 256) ? __ldg(g_qnorm + tid - 128)
                              : __ldg(g_knorm + tid - 256);
        sm[OFF_G + tid] = v;
    }
    // chunk-0 W STS (overlaps halo LDG latency)
    #pragma unroll
    for (int t = 0; t < 2; ++t) {
        int w4 = tid + t * 512;
        int row = w4 >> 3, colw = (w4 & 7) * 4;
        *(uint4*)(smc + ARENA_F * 4 + WHI + row * 144 + colw * 4) = wph4[t];
        *(uint4*)(smc + ARENA_F * 4 + WLO + row * 144 + colw * 4) = wpl4[t];
    }
    // prefetch W chunk 1 into regs
    #pragma unroll
    for (int t = 0; t < 2; ++t) {
        int w4 = tid + t * 512;
        int row = w4 >> 3, colw = (w4 & 7) * 4;
        wph4[t] = *(const uint4*)&g_whi[1][row * 36 + colw];
        wpl4[t] = *(const uint4*)&g_wlo[1][row * 36 + colw];
    }
    __syncthreads();

    // ============ phase 1: expand (HMMA) + depthwise, 3 chunks ============
    for (int c = 0; c < 3; ++c) {
        // HMMA: warp = (mg: 32 o-rows) x (ng: nt range). A-frags cached in regs.
        {
            const int mg = warp & 3, ng = warp >> 2;
            const int nt0 = (ng == 0) ? 0 : 3 * ng + 1;
            const int cnt = (ng == 0) ? 4 : 3;
            uint32_t ahi[2][4][4], alo[2][4][4];
            #pragma unroll
            for (int mt = 0; mt < 2; ++mt) {
                uint32_t aH = arena + WHI + (mg * 32 + mt * 16 + (lane & 15)) * 144
                              + (lane >> 4) * 16;
                #pragma unroll
                for (int ks = 0; ks < 4; ++ks) {
                    ldsm4(ahi[mt][ks], aH + ks * 32);
                    ldsm4(alo[mt][ks], aH + (WLO - WHI) + ks * 32);
                }
            }
            for (int t = 0; t < cnt; ++t) {
                int nt = nt0 + t;
                float acc[2][4] = {};
                // B hi+lo via ONE ldsm4: lanes 0-15 hi tile, 16-31 lo tile
                const uint32_t bB = arena + XHI + (lane >> 4) * (XLO - XHI)
                                    + (nt * 8 + (lane & 7)) * 144
                                    + ((lane >> 3) & 1) * 16;
                #pragma unroll
                for (int ks = 0; ks < 4; ++ks) {
                    uint32_t bf[4];
                    ldsm4(bf, bB + ks * 32);
                    #pragma unroll
                    for (int mt = 0; mt < 2; ++mt) {
                        mma16816(acc[mt], ahi[mt][ks], bf[0], bf[1]);
                        mma16816(acc[mt], ahi[mt][ks], bf[2], bf[3]);
                        mma16816(acc[mt], alo[mt][ks], bf[0], bf[1]);
                    }
                }
                int p = nt * 8 + 2 * (lane & 3);
                #pragma unroll
                for (int mt = 0; mt < 2; ++mt) {
                    int o = mg * 32 + mt * 16 + (lane >> 2);
                    if (p < 100) {
                        sm[OFF_HID + o * 101 + p]       = acc[mt][0];
                        sm[OFF_HID + (o + 8) * 101 + p] = acc[mt][2];
                    }
                    if (p + 1 < 100) {
                        sm[OFF_HID + o * 101 + p + 1]       = acc[mt][1];
                        sm[OFF_HID + (o + 8) * 101 + p + 1] = acc[mt][3];
                    }
                }
            }
        }
        __syncthreads();   // HID ready; W arena dead

        // STS W[c+1] (overlaps dw conv; disjoint smem regions)
        if (c < 2) {
            #pragma unroll
            for (int t = 0; t < 2; ++t) {
                int w4 = tid + t * 512;
                int row = w4 >> 3, colw = (w4 & 7) * 4;
                *(uint4*)(smc + ARENA_F * 4 + WHI + row * 144 + colw * 4) = wph4[t];
                *(uint4*)(smc + ARENA_F * 4 + WLO + row * 144 + colw * 4) = wpl4[t];
            }
            if (c < 1) {
                #pragma unroll
                for (int t = 0; t < 2; ++t) {
                    int w4 = tid + t * 512;
                    int row = w4 >> 3, colw = (w4 & 7) * 4;
                    wph4[t] = *(const uint4*)&g_whi[2][row * 36 + colw];
                    wpl4[t] = *(const uint4*)&g_wlo[2][row * 36 + colw];
                }
            }
        }

        // depthwise 3x3 (f32x2), weights in regs; thread = (channel, 2-col group)
        {
            int g = tid >> 7;
            uint64_t ww[9];
            #pragma unroll
            for (int t = 0; t < 9; ++t) ww[t] = pk2(dwv[t], dwv[t]);
            const float* hb = &sm[OFF_HID + dwch * 101 + 2 * g];
            uint64_t Ap[3], Bp[3], Cp[3];
            {
                float a0 = hb[0], a1 = hb[1], a2 = hb[2], a3 = hb[3];
                Ap[0] = pk2(a0, a1); Ap[1] = pk2(a1, a2); Ap[2] = pk2(a2, a3);
                float b0 = hb[10], b1 = hb[11], b2 = hb[12], b3 = hb[13];
                Bp[0] = pk2(b0, b1); Bp[1] = pk2(b1, b2); Bp[2] = pk2(b2, b3);
            }
            float* qrow = &sm[OFF_QKV + (c * 128 + dwch) * 65 + 2 * g];
            #pragma unroll
            for (int r = 2; r < 10; ++r) {
                float c0 = hb[r*10+0], c1 = hb[r*10+1], c2 = hb[r*10+2], c3 = hb[r*10+3];
                Cp[0] = pk2(c0, c1); Cp[1] = pk2(c1, c2); Cp[2] = pk2(c2, c3);
                uint64_t s2 = pk2(0.f, 0.f);
                fma2(s2, ww[0], Ap[0]); fma2(s2, ww[1], Ap[1]); fma2(s2, ww[2], Ap[2]);
                fma2(s2, ww[3], Bp[0]); fma2(s2, ww[4], Bp[1]); fma2(s2, ww[5], Bp[2]);
                fma2(s2, ww[6], Cp[0]); fma2(s2, ww[7], Cp[1]); fma2(s2, ww[8], Cp[2]);
                float o0, o1; upk2(o0, o1, s2);
                int yy = r - 2;
                qrow[yy * 8 + 0] = o0; qrow[yy * 8 + 1] = o1;
                Ap[0]=Bp[0]; Ap[1]=Bp[1]; Ap[2]=Bp[2];
                Bp[0]=Cp[0]; Bp[1]=Cp[1]; Bp[2]=Cp[2];
            }
        }
        // prefetch dw weights for next chunk (covered by next HMMA latency)
        if (c < 2) {
            #pragma unroll
            for (int t = 0; t < 9; ++t)
                dwv[t] = __ldg(w_dw + ((c + 1) * 128 + dwch) * 9 + t);
        }
        __syncthreads();
    }

    // ---- prefetch w_proj (prepacked) into regs ----
    uint4 pjh[2], pjl[2];
    #pragma unroll
    for (int t = 0; t < 2; ++t) {
        int w4 = tid + t * 512;
        int row = w4 >> 4, colw = (w4 & 15) * 4;
        pjh[t] = *(const uint4*)&g_wph[row * 68 + colw];
        pjl[t] = *(const uint4*)&g_wpl[row * 68 + colw];
    }

    // ---- phase 2: RMS factors for q and k (warp -> 4 pixels) ----
    #pragma unroll
    for (int pi = 0; pi < 4; ++pi) {
        int pix = warp * 4 + pi;
        float sq = 0.f, sk = 0.f;
        #pragma unroll
        for (int r = 0; r < 4; ++r) {
            int cc = lane + r * 32;
            float qv = sm[OFF_QKV + cc * 65 + pix];
            float kv = sm[OFF_QKV + (128 + cc) * 65 + pix];
            sq = fmaf(qv, qv, sq);
            sk = fmaf(kv, kv, sk);
        }
        #pragma unroll
        for (int off = 16; off; off >>= 1) {
            sq += __shfl_xor_sync(0xffffffffu, sq, off);
            sk += __shfl_xor_sync(0xffffffffu, sk, off);
        }
        if (lane == 0) {
            sm[OFF_RQ + pix] = rsqrtf(sq * (1.f / 128.f) + EPSF);
            sm[OFF_RK + pix] = rsqrtf(sk * (1.f / 128.f) + EPSF);
        }
    }
    __syncthreads();

    // ---- phase 3: RMSNorm scale + 2D RoPE (table-driven) ----
    for (int idx = tid; idx < 64 * 64; idx += 512) {
        int m = idx >> 6, pix = idx & 63;
        int flag = (m >> 5), mm = m & 31;
        int d = flag ? (pix & 7) : (pix >> 3);
        float cs = sm[OFF_SC + flag * 256 + mm * 8 + d];
        float sn = sm[OFF_SC + 512 + flag * 256 + mm * 8 + d];
        int c0 = 2 * m;
        float rqp = sm[OFF_RQ + pix], rkp = sm[OFF_RK + pix];
        float gq0 = sm[OFF_G + 128 + c0], gq1 = sm[OFF_G + 129 + c0];
        float gk0 = sm[OFF_G + 256 + c0], gk1 = sm[OFF_G + 257 + c0];

        float q0 = sm[OFF_QKV + c0 * 65 + pix]       * rqp * gq0;
        float q1 = sm[OFF_QKV + (c0 + 1) * 65 + pix] * rqp * gq1;
        sm[OFF_QKV + c0 * 65 + pix]       = q0 * cs - q1 * sn;
        sm[OFF_QKV + (c0 + 1) * 65 + pix] = q1 * cs + q0 * sn;

        float k0 = sm[OFF_QKV + (128 + c0) * 65 + pix] * rkp * gk0;
        float k1 = sm[OFF_QKV + (129 + c0) * 65 + pix] * rkp * gk1;
        sm[OFF_QKV + (128 + c0) * 65 + pix] = k0 * cs - k1 * sn;
        sm[OFF_QKV + (129 + c0) * 65 + pix] = k1 * cs + k0 * sn;
    }
    __syncthreads();   // QKV (q,k) final before circ conv reads

    // ---- phase 4: circ conv (f32x2 parity-split) + w_proj STS overlapped ----
    {
        const int cc = tid & 127;
        const int A0 = ((tid >> 7) & 1) * 4;
        const int P  = tid >> 8;
        const float* qb = &sm[OFF_QKV + cc * 65];
        const float* kb = &sm[OFF_QKV + (128 + cc) * 65];
        float v32[32];
        if (P == 0) circ_par<0>(qb, kb, A0, v32);
        else        circ_par<1>(qb, kb, A0, v32);

        // w_proj tiles via uint4 copy (phase-1 arena dead; disjoint from scratch)
        #pragma unroll
        for (int t = 0; t < 2; ++t) {
            int w4 = tid + t * 512;
            int row = w4 >> 4, colw = (w4 & 15) * 4;
            *(uint4*)(smc + ARENA_F * 4 + WPH + row * 272 + colw * 4) = pjh[t];
            *(uint4*)(smc + ARENA_F * 4 + WPL + row * 272 + colw * 4) = pjl[t];
        }

        float* scratch = (float*)(smc + ARENA_F * 4 + CBH);   // 256 x 33 floats
        int s = tid & 255;
        if (P == 1) {
            #pragma unroll
            for (int t = 0; t < 32; ++t) scratch[s * 33 + t] = v32[t];
        }
        __syncthreads();
        if (P == 0) {
            #pragma unroll
            for (int t = 0; t < 32; ++t) {
                float tot = v32[t] + scratch[s * 33 + t];
                sm[OFF_CORR + cc * 65 + (A0 + (t >> 3)) * 8 + (t & 7)] = tot;
            }
        }
    }
    __syncthreads();

    // ---- phase 5: corr RMS factor (warp -> 4 pixels) ----
    #pragma unroll
    for (int pi = 0; pi < 4; ++pi) {
        int pix = warp * 4 + pi;
        float sc = 0.f;
        #pragma unroll
        for (int r = 0; r < 4; ++r) {
            float cv = sm[OFF_CORR + (lane + r * 32) * 65 + pix];
            sc = fmaf(cv, cv, sc);
        }
        #pragma unroll
        for (int off = 16; off; off >>= 1)
            sc += __shfl_xor_sync(0xffffffffu, sc, off);
        if (lane == 0)
            sm[OFF_RN + pix] = rsqrtf(sc * (1.f / 128.f) + EPSF);
    }
    __syncthreads();

    // ---- phase 6: (v * g_norm * rn * corr) -> bf16 hi/lo B tiles [pix][k] ----
    for (int idx = tid; idx < 64 * 64; idx += 512) {
        int pix = idx >> 6, kp = idx & 63;
        int k0 = 2 * kp;
        float rnp = sm[OFF_RN + pix];
        float c0v = sm[OFF_CORR + k0 * 65 + pix];
        float c1v = sm[OFF_CORR + (k0 + 1) * 65 + pix];
        float v0  = sm[OFF_QKV + (256 + k0) * 65 + pix];
        float v1  = sm[OFF_QKV + (257 + k0) * 65 + pix];
        float w0 = v0 * c0v * rnp * sm[OFF_G + k0];
        float w1 = v1 * c1v * rnp * sm[OFF_G + k0 + 1];
        uint32_t lp, hp = pack_hi_lo(w0, w1, lp);
        *(uint32_t*)(smc + ARENA_F * 4 + CBH + pix * 272 + kp * 4) = hp;
        *(uint32_t*)(smc + ARENA_F * 4 + CBL + pix * 272 + kp * 4) = lp;
    }
    __syncthreads();

    // ---- phase 7: projection HMMA on 16 warps (4 mg x 4 nh, 2 nt each) ----
    {
        const int mg = warp & 3, nh = warp >> 2;
        uint32_t ahw[8][4], alw[8][4];
        const uint32_t aH = arena + WPH + (mg * 16 + (lane & 15)) * 272
                            + (lane >> 4) * 16;
        #pragma unroll
        for (int ks = 0; ks < 8; ++ks) {
            ldsm4(ahw[ks], aH + ks * 32);
            ldsm4(alw[ks], aH + (WPL - WPH) + ks * 32);
        }
        float* ob = out + (size_t)b * 64 * HH * WW;
        #pragma unroll
        for (int t = 0; t < 2; ++t) {
            int nt = nh * 2 + t;
            float acc[4] = {};
            const uint32_t bB = arena + CBH + (lane >> 4) * (CBL - CBH)
                                + (nt * 8 + (lane & 7)) * 272
                                + ((lane >> 3) & 1) * 16;
            #pragma unroll
            for (int ks = 0; ks < 8; ++ks) {
                uint32_t bf[4];
                ldsm4(bf, bB + ks * 32);
                mma16816(acc, ahw[ks], bf[0], bf[1]);
                mma16816(acc, ahw[ks], bf[2], bf[3]);
                mma16816(acc, alw[ks], bf[0], bf[1]);
            }
            int o = mg * 16 + (lane >> 2);
            int gy = gy0 + nt;
            int gxp = gx0 + 2 * (lane & 3);
            *(float2*)(ob + (size_t)o * (HH * WW) + gy * WW + gxp)
                = make_float2(acc[0], acc[1]);
            *(float2*)(ob + (size_t)(o + 8) * (HH * WW) + gy * WW + gxp)
                = make_float2(acc[2], acc[3]);
        }
    }
}

extern "C" void kernel_launch(void* const* d_in, const int* in_sizes, int n_in,
                              void* d_out, int out_size)
{
    (void)in_sizes; (void)n_in; (void)out_size;
    const float* x        = (const float*)d_in[0];
    const float* w_hidden = (const float*)d_in[1];
    const float* w_dw     = (const float*)d_in[2];
    const float* w_proj   = (const float*)d_in[3];
    const float* g_norm   = (const float*)d_in[4];
    const float* g_qnorm  = (const float*)d_in[5];
    const float* g_knorm  = (const float*)d_in[6];
    float* out = (float*)d_out;

    prep_weights<<<64, 256>>>(w_hidden, w_proj);

    cudaFuncSetAttribute(fsas_fused_kernel,
                         cudaFuncAttributeMaxDynamicSharedMemorySize, SMEM_BYTES);
    dim3 grid(WW / 8, HH / 8, 4);
    fsas_fused_kernel<<<grid, 512, SMEM_BYTES>>>(
        x, w_dw, g_norm, g_qnorm, g_knorm, out);
}

// round 14
// speedup vs baseline: 1.0133x; 1.0133x over previous
// FSAS_V5 fused forward — one CTA per 8x8 patch, 512 threads.
// R14 = R12 (best: 631us) + ONE change: B-fragment hi/lo tiles fetched with a
// single ldsm4 (lanes 0-15 hi tile, 16-31 lo tile) in expand + proj HMMA.
#include <cuda_runtime.h>
#include <cuda_bf16.h>
#include <cstdint>

#define HH 256
#define WW 256
#define EPSF 1e-6f
#define L2T_OVER_32 0.41524101186092030f

// ---- dynamic smem layout (float offsets) ----
#define OFF_QKV  0                 // 384 * 65 fp32
#define OFF_HID  24960             // 128 * 101 fp32 hidden chunk
#define OFF_CORR OFF_HID           // 128 * 65 overlay (phase 4+)
#define OFF_G    37888             // g_norm[128], g_qnorm[128], g_knorm[128]
#define OFF_SC   38272             // sincos: cos[512], sin[512]
#define OFF_DW   39296             // 128*9 dw weights (per chunk)
#define OFF_RQ   40448
#define OFF_RK   40512
#define OFF_RN   40576
#define ARENA_F  40640             // bf16 tile arena @ byte 162,560
// phase-1 arena (rows strided 144 B -> ldmatrix conflict-free)
#define XHI 0
#define XLO 14976
#define WHI 29952
#define WLO 48384
// proj arena (rows strided 272 B) — SAME bytes as phase-1 arena, reused later
#define WPH 0
#define WPL 17408
#define CBH 34816
#define CBL 52224
#define ARENA_BYTES 69632
#define SMEM_BYTES (ARENA_F * 4 + ARENA_BYTES)   // 232,192 B

// ---- prepacked weights (constant across CTAs) ----
__device__ uint32_t g_whi[3][128 * 36];   // w_hidden hi, rows 144 B
__device__ uint32_t g_wlo[3][128 * 36];   // w_hidden lo
__device__ uint32_t g_wph[64 * 68];       // w_proj hi, rows 272 B
__device__ uint32_t g_wpl[64 * 68];       // w_proj lo

__device__ __forceinline__ uint32_t smem_u32(const void* p) {
    uint32_t a;
    asm("{ .reg .u64 t; cvta.to.shared.u64 t, %1; cvt.u32.u64 %0, t; }"
        : "=r"(a) : "l"(p));
    return a;
}
__device__ __forceinline__ void ldsm4(uint32_t* r, uint32_t addr) {
    asm volatile("ldmatrix.sync.aligned.m8n8.x4.shared.b16 {%0,%1,%2,%3}, [%4];"
                 : "=r"(r[0]), "=r"(r[1]), "=r"(r[2]), "=r"(r[3]) : "r"(addr));
}
__device__ __forceinline__ void mma16816(float* c, const uint32_t* a,
                                         uint32_t b0, uint32_t b1) {
    asm volatile("mma.sync.aligned.m16n8k16.row.col.f32.bf16.bf16.f32 "
                 "{%0,%1,%2,%3}, {%4,%5,%6,%7}, {%8,%9}, {%0,%1,%2,%3};"
                 : "+f"(c[0]), "+f"(c[1]), "+f"(c[2]), "+f"(c[3])
                 : "r"(a[0]), "r"(a[1]), "r"(a[2]), "r"(a[3]), "r"(b0), "r"(b1));
}
__device__ __forceinline__ uint32_t pack_hi_lo(float v0, float v1, uint32_t& lo) {
    __nv_bfloat16 h0 = __float2bfloat16(v0);
    __nv_bfloat16 h1 = __float2bfloat16(v1);
    __nv_bfloat16 l0 = __float2bfloat16(v0 - __bfloat162float(h0));
    __nv_bfloat16 l1 = __float2bfloat16(v1 - __bfloat162float(h1));
    lo = ((uint32_t)__bfloat16_as_ushort(l1) << 16) | __bfloat16_as_ushort(l0);
    return ((uint32_t)__bfloat16_as_ushort(h1) << 16) | __bfloat16_as_ushort(h0);
}
// ---- packed f32x2 helpers ----
__device__ __forceinline__ uint64_t pk2(float lo, float hi) {
    uint64_t r; asm("mov.b64 %0, {%1, %2};" : "=l"(r) : "f"(lo), "f"(hi)); return r;
}
__device__ __forceinline__ void upk2(float& lo, float& hi, uint64_t v) {
    asm("mov.b64 {%0, %1}, %2;" : "=f"(lo), "=f"(hi) : "l"(v));
}
__device__ __forceinline__ void fma2(uint64_t& d, uint64_t a, uint64_t b) {
    asm("fma.rn.f32x2 %0, %1, %2, %0;" : "+l"(d) : "l"(a), "l"(b));
}

// circ conv body, i-parity P compile-time (see R9).
template<int P>
__device__ __forceinline__ void circ_par(const float* qb, const float* kb,
                                         int A0, float* outv)
{
    uint64_t krp[4][8];
    #pragma unroll
    for (int t = 0; t < 4; ++t) {
        #pragma unroll
        for (int c = 0; c < 8; ++c) {
            int r0 = (2*t + P + A0) & 7;
            int r1 = (2*t + P + 1 + A0) & 7;
            krp[t][c] = pk2(kb[r0*8 + c], kb[r1*8 + c]);
        }
    }
    uint64_t acc2[2][8];
    #pragma unroll
    for (int rp = 0; rp < 2; ++rp)
        #pragma unroll
        for (int bb = 0; bb < 8; ++bb) acc2[rp][bb] = pk2(0.f, 0.f);
    #pragma unroll
    for (int ii = 0; ii < 4; ++ii) {
        const int i = P + 2*ii;
        #pragma unroll
        for (int j = 0; j < 8; ++j) {
            float qs = qb[i*8 + j];
            uint64_t qq = pk2(qs, qs);
            #pragma unroll
            for (int rp = 0; rp < 2; ++rp) {
                const int t = (rp - P - ii) & 3;
                #pragma unroll
                for (int bb = 0; bb < 8; ++bb)
                    fma2(acc2[rp][bb], qq, krp[t][(bb - j) & 7]);
            }
        }
    }
    #pragma unroll
    for (int rp = 0; rp < 2; ++rp)
        #pragma unroll
        for (int bb = 0; bb < 8; ++bb)
            upk2(outv[(2*rp)*8 + bb], outv[(2*rp+1)*8 + bb], acc2[rp][bb]);
}

// ---- prep kernel: pack constant weights into arena layout ----
__global__ void prep_weights(const float* __restrict__ w_hidden,
                             const float* __restrict__ w_proj)
{
    int t = blockIdx.x * blockDim.x + threadIdx.x;
    if (t < 3 * 128 * 32) {
        int c = t >> 12, rem = t & 4095, r = rem >> 5, cp = rem & 31;
        float2 wv = ((const float2*)w_hidden)[(c * 128 + r) * 32 + cp];
        uint32_t lp, hp = pack_hi_lo(wv.x, wv.y, lp);
        g_whi[c][r * 36 + cp] = hp;
        g_wlo[c][r * 36 + cp] = lp;
    } else if (t < 3 * 128 * 32 + 64 * 64) {
        int i = t - 3 * 128 * 32;
        int o = i >> 6, kp = i & 63;
        float2 wv = ((const float2*)w_proj)[o * 64 + kp];
        uint32_t lp, hp = pack_hi_lo(wv.x, wv.y, lp);
        g_wph[o * 68 + kp] = hp;
        g_wpl[o * 68 + kp] = lp;
    }
}

__global__ __launch_bounds__(512, 1)
void fsas_fused_kernel(const float* __restrict__ x,
                       const float* __restrict__ w_dw,
                       const float* __restrict__ g_norm,
                       const float* __restrict__ g_qnorm,
                       const float* __restrict__ g_knorm,
                       float* __restrict__ out)
{
    extern __shared__ float sm[];
    const int tid  = threadIdx.x;
    const int lane = tid & 31;
    const int warp = tid >> 5;
    const int px = blockIdx.x, py = blockIdx.y, b = blockIdx.z;
    const int gx0 = px * 8, gy0 = py * 8;

    char* smc = (char*)sm;
    const uint32_t sbase = smem_u32(sm);
    const uint32_t arena = sbase + ARENA_F * 4;

    // ---- prefetch chunk 0 W (prepacked uint4) + dw ----
    uint4 wph4[2], wpl4[2];
    float dwpre[3];
    #pragma unroll
    for (int t = 0; t < 2; ++t) {
        int w4 = tid + t * 512;
        int row = w4 >> 3, colw = (w4 & 7) * 4;
        wph4[t] = *(const uint4*)&g_whi[0][row * 36 + colw];
        wpl4[t] = *(const uint4*)&g_wlo[0][row * 36 + colw];
    }
    #pragma unroll
    for (int t = 0; t < 3; ++t) {
        int idx = tid + t * 512;
        dwpre[t] = (idx < 1152) ? __ldg(w_dw + idx) : 0.f;
    }

    // ---- phase 0: x halo (COALESCED: lane = 4 ch-pairs x 8 consecutive pos) ----
    const float* xb = x + (size_t)b * 64 * HH * WW;
    for (int it = warp; it < 104; it += 16) {
        int cpBase = it / 13;
        int posBase = it - cpBase * 13;
        int cp  = cpBase * 4 + (lane >> 3);       // 0..31 channel-pair
        int pos = posBase * 8 + (lane & 7);       // 0..103
        float x0 = 0.f, x1 = 0.f;
        if (pos < 100) {
            int Y = pos / 10, X = pos - Y * 10;
            int gy = gy0 - 1 + Y, gx = gx0 - 1 + X;
            if ((unsigned)gy < HH && (unsigned)gx < WW) {
                size_t base = (size_t)(2 * cp) * (HH * WW) + gy * WW + gx;
                x0 = __ldg(xb + base);
                x1 = __ldg(xb + base + (size_t)(HH * WW));
            }
        }
        uint32_t lp, hp = pack_hi_lo(x0, x1, lp);
        uint32_t off = (uint32_t)(pos * 144 + cp * 4);
        *(uint32_t*)(smc + ARENA_F * 4 + XHI + off) = hp;
        *(uint32_t*)(smc + ARENA_F * 4 + XLO + off) = lp;
    }
    {   // sincos table
        int flag = tid >> 8, mm = (tid >> 3) & 31, d = tid & 7;
        float pos = (float)((flag ? gx0 : gy0) + d);
        float inv = exp2f(-L2T_OVER_32 * (float)mm);
        float sn, cs;
        sincosf(pos * inv, &sn, &cs);
        sm[OFF_SC + flag * 256 + mm * 8 + d]       = cs;
        sm[OFF_SC + 512 + flag * 256 + mm * 8 + d] = sn;
    }
    if (tid < 384) {
        float v = (tid < 128) ? __ldg(g_norm + tid)
                : (tid < 256) ? __ldg(g_qnorm + tid - 128)
                              : __ldg(g_knorm + tid - 256);
        sm[OFF_G + tid] = v;
    }
    // chunk-0 W/dw STS hoisted here (overlaps the halo LDG latency)
    #pragma unroll
    for (int t = 0; t < 2; ++t) {
        int w4 = tid + t * 512;
        int row = w4 >> 3, colw = (w4 & 7) * 4;
        *(uint4*)(smc + ARENA_F * 4 + WHI + row * 144 + colw * 4) = wph4[t];
        *(uint4*)(smc + ARENA_F * 4 + WLO + row * 144 + colw * 4) = wpl4[t];
    }
    #pragma unroll
    for (int t = 0; t < 3; ++t) {
        int idx = tid + t * 512;
        if (idx < 1152) sm[OFF_DW + idx] = dwpre[t];
    }
    __syncthreads();

    // ============ phase 1: expand (HMMA) + depthwise, 3 chunks ============
    for (int c = 0; c < 3; ++c) {
        if (c > 0) {
            #pragma unroll
            for (int t = 0; t < 2; ++t) {
                int w4 = tid + t * 512;
                int row = w4 >> 3, colw = (w4 & 7) * 4;
                *(uint4*)(smc + ARENA_F * 4 + WHI + row * 144 + colw * 4) = wph4[t];
                *(uint4*)(smc + ARENA_F * 4 + WLO + row * 144 + colw * 4) = wpl4[t];
            }
            #pragma unroll
            for (int t = 0; t < 3; ++t) {
                int idx = tid + t * 512;
                if (idx < 1152) sm[OFF_DW + idx] = dwpre[t];
            }
            __syncthreads();
        }
        // prefetch next chunk (hidden under HMMA)
        if (c < 2) {
            #pragma unroll
            for (int t = 0; t < 2; ++t) {
                int w4 = tid + t * 512;
                int row = w4 >> 3, colw = (w4 & 7) * 4;
                wph4[t] = *(const uint4*)&g_whi[c + 1][row * 36 + colw];
                wpl4[t] = *(const uint4*)&g_wlo[c + 1][row * 36 + colw];
            }
            #pragma unroll
            for (int t = 0; t < 3; ++t) {
                int idx = tid + t * 512;
                dwpre[t] = (idx < 1152) ? __ldg(w_dw + (c + 1) * 1152 + idx) : 0.f;
            }
        }

        // HMMA: warp = (mg: 32 o-rows) x (ng: nt range). A-frags cached in regs.
        {
            const int mg = warp & 3, ng = warp >> 2;
            const int nt0 = (ng == 0) ? 0 : 3 * ng + 1;
            const int cnt = (ng == 0) ? 4 : 3;
            uint32_t ahi[2][4][4], alo[2][4][4];
            #pragma unroll
            for (int mt = 0; mt < 2; ++mt) {
                uint32_t aH = arena + WHI + (mg * 32 + mt * 16 + (lane & 15)) * 144
                              + (lane >> 4) * 16;
                #pragma unroll
                for (int ks = 0; ks < 4; ++ks) {
                    ldsm4(ahi[mt][ks], aH + ks * 32);
                    ldsm4(alo[mt][ks], aH + (WLO - WHI) + ks * 32);
                }
            }
            for (int t = 0; t < cnt; ++t) {
                int nt = nt0 + t;
                float acc[2][4] = {};
                // B hi+lo via ONE ldsm4: lanes 0-15 hi tile, 16-31 lo tile
                const uint32_t bB = arena + XHI + (lane >> 4) * (XLO - XHI)
                                    + (nt * 8 + (lane & 7)) * 144
                                    + ((lane >> 3) & 1) * 16;
                #pragma unroll
                for (int ks = 0; ks < 4; ++ks) {
                    uint32_t bf[4];
                    ldsm4(bf, bB + ks * 32);
                    #pragma unroll
                    for (int mt = 0; mt < 2; ++mt) {
                        mma16816(acc[mt], ahi[mt][ks], bf[0], bf[1]);   // hi*hi
                        mma16816(acc[mt], ahi[mt][ks], bf[2], bf[3]);   // hi*lo
                        mma16816(acc[mt], alo[mt][ks], bf[0], bf[1]);   // lo*hi
                    }
                }
                int p = nt * 8 + 2 * (lane & 3);
                #pragma unroll
                for (int mt = 0; mt < 2; ++mt) {
                    int o = mg * 32 + mt * 16 + (lane >> 2);
                    if (p < 100) {
                        sm[OFF_HID + o * 101 + p]       = acc[mt][0];
                        sm[OFF_HID + (o + 8) * 101 + p] = acc[mt][2];
                    }
                    if (p + 1 < 100) {
                        sm[OFF_HID + o * 101 + p + 1]       = acc[mt][1];
                        sm[OFF_HID + (o + 8) * 101 + p + 1] = acc[mt][3];
                    }
                }
            }
        }
        __syncthreads();

        // depthwise 3x3 (f32x2), thread = (channel, 2-col group), rolling rows
        {
            int ch = tid & 127, g = tid >> 7;
            const float* wd = &sm[OFF_DW + ch * 9];
            uint64_t ww[9];
            #pragma unroll
            for (int t = 0; t < 9; ++t) { float w = wd[t]; ww[t] = pk2(w, w); }
            const float* hb = &sm[OFF_HID + ch * 101 + 2 * g];
            uint64_t Ap[3], Bp[3], Cp[3];
            {
                float a0 = hb[0], a1 = hb[1], a2 = hb[2], a3 = hb[3];
                Ap[0] = pk2(a0, a1); Ap[1] = pk2(a1, a2); Ap[2] = pk2(a2, a3);
                float b0 = hb[10], b1 = hb[11], b2 = hb[12], b3 = hb[13];
                Bp[0] = pk2(b0, b1); Bp[1] = pk2(b1, b2); Bp[2] = pk2(b2, b3);
            }
            float* qrow = &sm[OFF_QKV + (c * 128 + ch) * 65 + 2 * g];
            #pragma unroll
            for (int r = 2; r < 10; ++r) {
                float c0 = hb[r*10+0], c1 = hb[r*10+1], c2 = hb[r*10+2], c3 = hb[r*10+3];
                Cp[0] = pk2(c0, c1); Cp[1] = pk2(c1, c2); Cp[2] = pk2(c2, c3);
                uint64_t s2 = pk2(0.f, 0.f);
                fma2(s2, ww[0], Ap[0]); fma2(s2, ww[1], Ap[1]); fma2(s2, ww[2], Ap[2]);
                fma2(s2, ww[3], Bp[0]); fma2(s2, ww[4], Bp[1]); fma2(s2, ww[5], Bp[2]);
                fma2(s2, ww[6], Cp[0]); fma2(s2, ww[7], Cp[1]); fma2(s2, ww[8], Cp[2]);
                float o0, o1; upk2(o0, o1, s2);
                int yy = r - 2;
                qrow[yy * 8 + 0] = o0; qrow[yy * 8 + 1] = o1;
                Ap[0]=Bp[0]; Ap[1]=Bp[1]; Ap[2]=Bp[2];
                Bp[0]=Cp[0]; Bp[1]=Cp[1]; Bp[2]=Cp[2];
            }
        }
        __syncthreads();
    }

    // ---- prefetch w_proj (prepacked) into regs ----
    uint4 pjh[2], pjl[2];
    #pragma unroll
    for (int t = 0; t < 2; ++t) {
        int w4 = tid + t * 512;
        int row = w4 >> 4, colw = (w4 & 15) * 4;
        pjh[t] = *(const uint4*)&g_wph[row * 68 + colw];
        pjl[t] = *(const uint4*)&g_wpl[row * 68 + colw];
    }

    // ---- phase 2: RMS factors for q and k (warp -> 4 pixels) ----
    #pragma unroll
    for (int pi = 0; pi < 4; ++pi) {
        int pix = warp * 4 + pi;
        float sq = 0.f, sk = 0.f;
        #pragma unroll
        for (int r = 0; r < 4; ++r) {
            int cc = lane + r * 32;
            float qv = sm[OFF_QKV + cc * 65 + pix];
            float kv = sm[OFF_QKV + (128 + cc) * 65 + pix];
            sq = fmaf(qv, qv, sq);
            sk = fmaf(kv, kv, sk);
        }
        #pragma unroll
        for (int off = 16; off; off >>= 1) {
            sq += __shfl_xor_sync(0xffffffffu, sq, off);
            sk += __shfl_xor_sync(0xffffffffu, sk, off);
        }
        if (lane == 0) {
            sm[OFF_RQ + pix] = rsqrtf(sq * (1.f / 128.f) + EPSF);
            sm[OFF_RK + pix] = rsqrtf(sk * (1.f / 128.f) + EPSF);
        }
    }
    __syncthreads();

    // ---- phase 3: RMSNorm scale + 2D RoPE (table-driven) ----
    for (int idx = tid; idx < 64 * 64; idx += 512) {
        int m = idx >> 6, pix = idx & 63;
        int flag = (m >> 5), mm = m & 31;
        int d = flag ? (pix & 7) : (pix >> 3);
        float cs = sm[OFF_SC + flag * 256 + mm * 8 + d];
        float sn = sm[OFF_SC + 512 + flag * 256 + mm * 8 + d];
        int c0 = 2 * m;
        float rqp = sm[OFF_RQ + pix], rkp = sm[OFF_RK + pix];
        float gq0 = sm[OFF_G + 128 + c0], gq1 = sm[OFF_G + 129 + c0];
        float gk0 = sm[OFF_G + 256 + c0], gk1 = sm[OFF_G + 257 + c0];

        float q0 = sm[OFF_QKV + c0 * 65 + pix]       * rqp * gq0;
        float q1 = sm[OFF_QKV + (c0 + 1) * 65 + pix] * rqp * gq1;
        sm[OFF_QKV + c0 * 65 + pix]       = q0 * cs - q1 * sn;
        sm[OFF_QKV + (c0 + 1) * 65 + pix] = q1 * cs + q0 * sn;

        float k0 = sm[OFF_QKV + (128 + c0) * 65 + pix] * rkp * gk0;
        float k1 = sm[OFF_QKV + (129 + c0) * 65 + pix] * rkp * gk1;
        sm[OFF_QKV + (128 + c0) * 65 + pix] = k0 * cs - k1 * sn;
        sm[OFF_QKV + (129 + c0) * 65 + pix] = k1 * cs + k0 * sn;
    }

    // ---- phase 3.5: w_proj tiles via uint4 copy (phase-1 arena now dead) ----
    #pragma unroll
    for (int t = 0; t < 2; ++t) {
        int w4 = tid + t * 512;
        int row = w4 >> 4, colw = (w4 & 15) * 4;
        *(uint4*)(smc + ARENA_F * 4 + WPH + row * 272 + colw * 4) = pjh[t];
        *(uint4*)(smc + ARENA_F * 4 + WPL + row * 272 + colw * 4) = pjl[t];
    }
    __syncthreads();

    // ---- phase 4: circ conv, f32x2 parity-split ----
    {
        const int cc = tid & 127;
        const int A0 = ((tid >> 7) & 1) * 4;
        const int P  = tid >> 8;
        const float* qb = &sm[OFF_QKV + cc * 65];
        const float* kb = &sm[OFF_QKV + (128 + cc) * 65];
        float v32[32];
        if (P == 0) circ_par<0>(qb, kb, A0, v32);
        else        circ_par<1>(qb, kb, A0, v32);

        float* scratch = (float*)(smc + ARENA_F * 4 + CBH);   // 256 x 33 floats
        int s = tid & 255;
        if (P == 1) {
            #pragma unroll
            for (int t = 0; t < 32; ++t) scratch[s * 33 + t] = v32[t];
        }
        __syncthreads();
        if (P == 0) {
            #pragma unroll
            for (int t = 0; t < 32; ++t) {
                float tot = v32[t] + scratch[s * 33 + t];
                sm[OFF_CORR + cc * 65 + (A0 + (t >> 3)) * 8 + (t & 7)] = tot;
            }
        }
    }
    __syncthreads();

    // ---- phase 5: corr RMS factor (warp -> 4 pixels) ----
    #pragma unroll
    for (int pi = 0; pi < 4; ++pi) {
        int pix = warp * 4 + pi;
        float sc = 0.f;
        #pragma unroll
        for (int r = 0; r < 4; ++r) {
            float cv = sm[OFF_CORR + (lane + r * 32) * 65 + pix];
            sc = fmaf(cv, cv, sc);
        }
        #pragma unroll
        for (int off = 16; off; off >>= 1)
            sc += __shfl_xor_sync(0xffffffffu, sc, off);
        if (lane == 0)
            sm[OFF_RN + pix] = rsqrtf(sc * (1.f / 128.f) + EPSF);
    }
    __syncthreads();

    // ---- phase 6: (v * g_norm * rn * corr) -> bf16 hi/lo B tiles [pix][k] ----
    for (int idx = tid; idx < 64 * 64; idx += 512) {
        int pix = idx >> 6, kp = idx & 63;
        int k0 = 2 * kp;
        float rnp = sm[OFF_RN + pix];
        float c0v = sm[OFF_CORR + k0 * 65 + pix];
        float c1v = sm[OFF_CORR + (k0 + 1) * 65 + pix];
        float v0  = sm[OFF_QKV + (256 + k0) * 65 + pix];
        float v1  = sm[OFF_QKV + (257 + k0) * 65 + pix];
        float w0 = v0 * c0v * rnp * sm[OFF_G + k0];
        float w1 = v1 * c1v * rnp * sm[OFF_G + k0 + 1];
        uint32_t lp, hp = pack_hi_lo(w0, w1, lp);
        *(uint32_t*)(smc + ARENA_F * 4 + CBH + pix * 272 + kp * 4) = hp;
        *(uint32_t*)(smc + ARENA_F * 4 + CBL + pix * 272 + kp * 4) = lp;
    }
    __syncthreads();

    // ---- phase 7: projection HMMA on 16 warps (4 mg x 4 nh, 2 nt each) ----
    {
        const int mg = warp & 3, nh = warp >> 2;
        uint32_t ahw[8][4], alw[8][4];
        const uint32_t aH = arena + WPH + (mg * 16 + (lane & 15)) * 272
                            + (lane >> 4) * 16;
        #pragma unroll
        for (int ks = 0; ks < 8; ++ks) {
            ldsm4(ahw[ks], aH + ks * 32);
            ldsm4(alw[ks], aH + (WPL - WPH) + ks * 32);
        }
        float* ob = out + (size_t)b * 64 * HH * WW;
        #pragma unroll
        for (int t = 0; t < 2; ++t) {
            int nt = nh * 2 + t;
            float acc[4] = {};
            // B hi+lo via ONE ldsm4: lanes 0-15 hi tile, 16-31 lo tile
            const uint32_t bB = arena + CBH + (lane >> 4) * (CBL - CBH)
                                + (nt * 8 + (lane & 7)) * 272
                                + ((lane >> 3) & 1) * 16;
            #pragma unroll
            for (int ks = 0; ks < 8; ++ks) {
                uint32_t bf[4];
                ldsm4(bf, bB + ks * 32);
                mma16816(acc, ahw[ks], bf[0], bf[1]);   // hi*hi
                mma16816(acc, ahw[ks], bf[2], bf[3]);   // hi*lo
                mma16816(acc, alw[ks], bf[0], bf[1]);   // lo*hi
            }
            int o = mg * 16 + (lane >> 2);
            int gy = gy0 + nt;
            int gxp = gx0 + 2 * (lane & 3);
            *(float2*)(ob + (size_t)o * (HH * WW) + gy * WW + gxp)
                = make_float2(acc[0], acc[1]);
            *(float2*)(ob + (size_t)(o + 8) * (HH * WW) + gy * WW + gxp)
                = make_float2(acc[2], acc[3]);
        }
    }
}

extern "C" void kernel_launch(void* const* d_in, const int* in_sizes, int n_in,
                              void* d_out, int out_size)
{
    (void)in_sizes; (void)n_in; (void)out_size;
    const float* x        = (const float*)d_in[0];
    const float* w_hidden = (const float*)d_in[1];
    const float* w_dw     = (const float*)d_in[2];
    const float* w_proj   = (const float*)d_in[3];
    const float* g_norm   = (const float*)d_in[4];
    const float* g_qnorm  = (const float*)d_in[5];
    const float* g_knorm  = (const float*)d_in[6];
    float* out = (float*)d_out;

    prep_weights<<<64, 256>>>(w_hidden, w_proj);

    cudaFuncSetAttribute(fsas_fused_kernel,
                         cudaFuncAttributeMaxDynamicSharedMemorySize, SMEM_BYTES);
    dim3 grid(WW / 8, HH / 8, 4);
    fsas_fused_kernel<<<grid, 512, SMEM_BYTES>>>(
        x, w_dw, g_norm, g_qnorm, g_knorm, out);
}

// round 15
// speedup vs baseline: 1.0753x; 1.0611x over previous
// FSAS_V5 fused forward — one CTA per 8x8 patch, 512 threads.
// R15: A-operands (w_hidden, w_proj) prepacked into mma FRAGMENT layout in
// __device__ globals; main kernel fills A-frags via coalesced LDG.128 (L2-hit,
// prefetched) — no W smem staging, no A-ldsm, 4 fewer barriers. dw weights
// double-buffered in the freed W-arena.
#include <cuda_runtime.h>
#include <cuda_bf16.h>
#include <cstdint>

#define HH 256
#define WW 256
#define EPSF 1e-6f
#define L2T_OVER_32 0.41524101186092030f

// ---- dynamic smem layout (float offsets) ----
#define OFF_QKV  0                 // 384 * 65 fp32
#define OFF_HID  24960             // 128 * 101 fp32 hidden chunk
#define OFF_CORR OFF_HID           // 128 * 65 overlay (phase 4+)
#define OFF_G    37888             // g_norm[128], g_qnorm[128], g_knorm[128]
#define OFF_SC   38272             // sincos: cos[512], sin[512]
#define OFF_RQ   40448
#define OFF_RK   40512
#define OFF_RN   40576
#define ARENA_F  40640             // bf16 tile arena @ byte 162,560
// phase-1 X tiles (rows strided 144 B -> ldmatrix conflict-free)
#define XHI 0
#define XLO 14976
#define DWB 29952                  // dw weight double buffer (2 x 4608 B), ph1 only
// phase 4+ arena (rows strided 272 B; reuses the same bytes)
#define CBH 34816
#define CBL 52224
#define ARENA_BYTES 69632
#define SMEM_BYTES (ARENA_F * 4 + ARENA_BYTES)   // 232,192 B

// ---- prepacked weight FRAGMENTS (constant across CTAs) ----
// expand: [chunk][slot*4 + r], slot = ((mg*2+mt)*4+ks)*32 + lane
__device__ uint32_t g_wfh[3][4096];
__device__ uint32_t g_wfl[3][4096];
// proj: slot = (mg*8+ks)*32 + lane
__device__ uint32_t g_pfh[4096];
__device__ uint32_t g_pfl[4096];

__device__ __forceinline__ uint32_t smem_u32(const void* p) {
    uint32_t a;
    asm("{ .reg .u64 t; cvta.to.shared.u64 t, %1; cvt.u32.u64 %0, t; }"
        : "=r"(a) : "l"(p));
    return a;
}
__device__ __forceinline__ void ldsm4(uint32_t* r, uint32_t addr) {
    asm volatile("ldmatrix.sync.aligned.m8n8.x4.shared.b16 {%0,%1,%2,%3}, [%4];"
                 : "=r"(r[0]), "=r"(r[1]), "=r"(r[2]), "=r"(r[3]) : "r"(addr));
}
__device__ __forceinline__ void mma16816v(float* c, uint4 a,
                                          uint32_t b0, uint32_t b1) {
    asm volatile("mma.sync.aligned.m16n8k16.row.col.f32.bf16.bf16.f32 "
                 "{%0,%1,%2,%3}, {%4,%5,%6,%7}, {%8,%9}, {%0,%1,%2,%3};"
                 : "+f"(c[0]), "+f"(c[1]), "+f"(c[2]), "+f"(c[3])
                 : "r"(a.x), "r"(a.y), "r"(a.z), "r"(a.w), "r"(b0), "r"(b1));
}
__device__ __forceinline__ uint32_t pack_hi_lo(float v0, float v1, uint32_t& lo) {
    __nv_bfloat16 h0 = __float2bfloat16(v0);
    __nv_bfloat16 h1 = __float2bfloat16(v1);
    __nv_bfloat16 l0 = __float2bfloat16(v0 - __bfloat162float(h0));
    __nv_bfloat16 l1 = __float2bfloat16(v1 - __bfloat162float(h1));
    lo = ((uint32_t)__bfloat16_as_ushort(l1) << 16) | __bfloat16_as_ushort(l0);
    return ((uint32_t)__bfloat16_as_ushort(h1) << 16) | __bfloat16_as_ushort(h0);
}
// ---- packed f32x2 helpers ----
__device__ __forceinline__ uint64_t pk2(float lo, float hi) {
    uint64_t r; asm("mov.b64 %0, {%1, %2};" : "=l"(r) : "f"(lo), "f"(hi)); return r;
}
__device__ __forceinline__ void upk2(float& lo, float& hi, uint64_t v) {
    asm("mov.b64 {%0, %1}, %2;" : "=f"(lo), "=f"(hi) : "l"(v));
}
__device__ __forceinline__ void fma2(uint64_t& d, uint64_t a, uint64_t b) {
    asm("fma.rn.f32x2 %0, %1, %2, %0;" : "+l"(d) : "l"(a), "l"(b));
}

// circ conv body, i-parity P compile-time (see R9).
template<int P>
__device__ __forceinline__ void circ_par(const float* qb, const float* kb,
                                         int A0, float* outv)
{
    uint64_t krp[4][8];
    #pragma unroll
    for (int t = 0; t < 4; ++t) {
        #pragma unroll
        for (int c = 0; c < 8; ++c) {
            int r0 = (2*t + P + A0) & 7;
            int r1 = (2*t + P + 1 + A0) & 7;
            krp[t][c] = pk2(kb[r0*8 + c], kb[r1*8 + c]);
        }
    }
    uint64_t acc2[2][8];
    #pragma unroll
    for (int rp = 0; rp < 2; ++rp)
        #pragma unroll
        for (int bb = 0; bb < 8; ++bb) acc2[rp][bb] = pk2(0.f, 0.f);
    #pragma unroll
    for (int ii = 0; ii < 4; ++ii) {
        const int i = P + 2*ii;
        #pragma unroll
        for (int j = 0; j < 8; ++j) {
            float qs = qb[i*8 + j];
            uint64_t qq = pk2(qs, qs);
            #pragma unroll
            for (int rp = 0; rp < 2; ++rp) {
                const int t = (rp - P - ii) & 3;
                #pragma unroll
                for (int bb = 0; bb < 8; ++bb)
                    fma2(acc2[rp][bb], qq, krp[t][(bb - j) & 7]);
            }
        }
    }
    #pragma unroll
    for (int rp = 0; rp < 2; ++rp)
        #pragma unroll
        for (int bb = 0; bb < 8; ++bb)
            upk2(outv[(2*rp)*8 + bb], outv[(2*rp+1)*8 + bb], acc2[rp][bb]);
}

// ---- prep kernel: pack weights into mma A-fragment layout ----
// frag reg r of lane l in a 16x16 block: row = (r&1)*8 + (l>>2),
//                                        col = ((r>>1)&1)*8 + (l&3)*2 (+1)
__global__ void prep_weights(const float* __restrict__ w_hidden,
                             const float* __restrict__ w_proj)
{
    int t = blockIdx.x * blockDim.x + threadIdx.x;
    if (t < 3072) {           // expand frags: 3 chunks x 1024 slots
        int c = t >> 10, s = t & 1023;
        int lane = s & 31, ks = (s >> 5) & 3, mt = (s >> 7) & 1, mg = s >> 8;
        #pragma unroll
        for (int r = 0; r < 4; ++r) {
            int row = c * 128 + mg * 32 + mt * 16 + (r & 1) * 8 + (lane >> 2);
            int col = ks * 16 + ((r >> 1) & 1) * 8 + (lane & 3) * 2;
            float v0 = w_hidden[row * 64 + col];
            float v1 = w_hidden[row * 64 + col + 1];
            uint32_t lp, hp = pack_hi_lo(v0, v1, lp);
            g_wfh[c][s * 4 + r] = hp;
            g_wfl[c][s * 4 + r] = lp;
        }
    } else if (t < 4096) {    // proj frags: 1024 slots
        int s = t - 3072;
        int lane = s & 31, ks = (s >> 5) & 7, mg = s >> 8;
        #pragma unroll
        for (int r = 0; r < 4; ++r) {
            int row = mg * 16 + (r & 1) * 8 + (lane >> 2);
            int col = ks * 16 + ((r >> 1) & 1) * 8 + (lane & 3) * 2;
            float v0 = w_proj[row * 128 + col];
            float v1 = w_proj[row * 128 + col + 1];
            uint32_t lp, hp = pack_hi_lo(v0, v1, lp);
            g_pfh[s * 4 + r] = hp;
            g_pfl[s * 4 + r] = lp;
        }
    }
}

__global__ __launch_bounds__(512, 1)
void fsas_fused_kernel(const float* __restrict__ x,
                       const float* __restrict__ w_dw,
                       const float* __restrict__ g_norm,
                       const float* __restrict__ g_qnorm,
                       const float* __restrict__ g_knorm,
                       float* __restrict__ out)
{
    extern __shared__ float sm[];
    const int tid  = threadIdx.x;
    const int lane = tid & 31;
    const int warp = tid >> 5;
    const int px = blockIdx.x, py = blockIdx.y, b = blockIdx.z;
    const int gx0 = px * 8, gy0 = py * 8;

    char* smc = (char*)sm;
    const uint32_t sbase = smem_u32(sm);
    const uint32_t arena = sbase + ARENA_F * 4;
    const int mg = warp & 3;

    // ---- prefetch: A-frags chunk 0 (LDG.128, L2-resident) + dw chunk 0 ----
    uint4 afh[2][4], afl[2][4];
    #pragma unroll
    for (int mt = 0; mt < 2; ++mt)
        #pragma unroll
        for (int ks = 0; ks < 4; ++ks) {
            int slot = ((mg * 2 + mt) * 4 + ks) * 32 + lane;
            afh[mt][ks] = *(const uint4*)&g_wfh[0][slot * 4];
            afl[mt][ks] = *(const uint4*)&g_wfl[0][slot * 4];
        }
    float dwpre[3];
    #pragma unroll
    for (int t = 0; t < 3; ++t) {
        int idx = tid + t * 512;
        dwpre[t] = (idx < 1152) ? __ldg(w_dw + idx) : 0.f;
    }

    // ---- phase 0: x halo (coalesced) -> bf16 hi/lo Xt tiles; sincos; g ----
    const float* xb = x + (size_t)b * 64 * HH * WW;
    for (int it = warp; it < 104; it += 16) {
        int cpBase = it / 13;
        int posBase = it - cpBase * 13;
        int cp  = cpBase * 4 + (lane >> 3);
        int pos = posBase * 8 + (lane & 7);
        float x0 = 0.f, x1 = 0.f;
        if (pos < 100) {
            int Y = pos / 10, X = pos - Y * 10;
            int gy = gy0 - 1 + Y, gx = gx0 - 1 + X;
            if ((unsigned)gy < HH && (unsigned)gx < WW) {
                size_t base = (size_t)(2 * cp) * (HH * WW) + gy * WW + gx;
                x0 = __ldg(xb + base);
                x1 = __ldg(xb + base + (size_t)(HH * WW));
            }
        }
        uint32_t lp, hp = pack_hi_lo(x0, x1, lp);
        uint32_t off = (uint32_t)(pos * 144 + cp * 4);
        *(uint32_t*)(smc + ARENA_F * 4 + XHI + off) = hp;
        *(uint32_t*)(smc + ARENA_F * 4 + XLO + off) = lp;
    }
    {   // sincos table
        int flag = tid >> 8, mm = (tid >> 3) & 31, d = tid & 7;
        float pos = (float)((flag ? gx0 : gy0) + d);
        float inv = exp2f(-L2T_OVER_32 * (float)mm);
        float sn, cs;
        sincosf(pos * inv, &sn, &cs);
        sm[OFF_SC + flag * 256 + mm * 8 + d]       = cs;
        sm[OFF_SC + 512 + flag * 256 + mm * 8 + d] = sn;
    }
    if (tid < 384) {
        float v = (tid < 128) ? __ldg(g_norm + tid)
                : (tid < 256) ? __ldg(g_qnorm + tid - 128)
                              : __ldg(g_knorm + tid - 256);
        sm[OFF_G + tid] = v;
    }
    // dw chunk 0 -> buffer 0 (overlaps halo LDG latency)
    {
        float* dwb0 = (float*)(smc + ARENA_F * 4 + DWB);
        #pragma unroll
        for (int t = 0; t < 3; ++t) {
            int idx = tid + t * 512;
            if (idx < 1152) dwb0[idx] = dwpre[t];
        }
    }
    // prefetch dw chunk 1 into regs
    #pragma unroll
    for (int t = 0; t < 3; ++t) {
        int idx = tid + t * 512;
        dwpre[t] = (idx < 1152) ? __ldg(w_dw + 1152 + idx) : 0.f;
    }
    __syncthreads();

    // ============ phase 1: expand (HMMA, A from regs) + depthwise ============
    for (int c = 0; c < 3; ++c) {
        // HMMA: warp = (mg: 32 o-rows) x (ng: nt range). A-frags in regs.
        {
            const int ng = warp >> 2;
            const int nt0 = (ng == 0) ? 0 : 3 * ng + 1;
            const int cnt = (ng == 0) ? 4 : 3;
            for (int t = 0; t < cnt; ++t) {
                int nt = nt0 + t;
                float acc[2][4] = {};
                // B hi+lo via ONE ldsm4: lanes 0-15 hi tile, 16-31 lo tile
                const uint32_t bB = arena + XHI + (lane >> 4) * (XLO - XHI)
                                    + (nt * 8 + (lane & 7)) * 144
                                    + ((lane >> 3) & 1) * 16;
                #pragma unroll
                for (int ks = 0; ks < 4; ++ks) {
                    uint32_t bf[4];
                    ldsm4(bf, bB + ks * 32);
                    #pragma unroll
                    for (int mt = 0; mt < 2; ++mt) {
                        mma16816v(acc[mt], afh[mt][ks], bf[0], bf[1]);   // hi*hi
                        mma16816v(acc[mt], afh[mt][ks], bf[2], bf[3]);   // hi*lo
                        mma16816v(acc[mt], afl[mt][ks], bf[0], bf[1]);   // lo*hi
                    }
                }
                int p = nt * 8 + 2 * (lane & 3);
                #pragma unroll
                for (int mt = 0; mt < 2; ++mt) {
                    int o = mg * 32 + mt * 16 + (lane >> 2);
                    if (p < 100) {
                        sm[OFF_HID + o * 101 + p]       = acc[mt][0];
                        sm[OFF_HID + (o + 8) * 101 + p] = acc[mt][2];
                    }
                    if (p + 1 < 100) {
                        sm[OFF_HID + o * 101 + p + 1]       = acc[mt][1];
                        sm[OFF_HID + (o + 8) * 101 + p + 1] = acc[mt][3];
                    }
                }
            }
        }
        __syncthreads();   // HID ready; A-frag regs dead

        // overlap with dw conv: A-frags(c+1) LDG, dw STS(c+1), dw LDG(c+2)
        if (c < 2) {
            #pragma unroll
            for (int mt = 0; mt < 2; ++mt)
                #pragma unroll
                for (int ks = 0; ks < 4; ++ks) {
                    int slot = ((mg * 2 + mt) * 4 + ks) * 32 + lane;
                    afh[mt][ks] = *(const uint4*)&g_wfh[c + 1][slot * 4];
                    afl[mt][ks] = *(const uint4*)&g_wfl[c + 1][slot * 4];
                }
            float* dwbn = (float*)(smc + ARENA_F * 4 + DWB + ((c + 1) & 1) * 4608);
            #pragma unroll
            for (int t = 0; t < 3; ++t) {
                int idx = tid + t * 512;
                if (idx < 1152) dwbn[idx] = dwpre[t];
            }
            if (c < 1) {
                #pragma unroll
                for (int t = 0; t < 3; ++t) {
                    int idx = tid + t * 512;
                    dwpre[t] = (idx < 1152) ? __ldg(w_dw + 2 * 1152 + idx) : 0.f;
                }
            }
        }

        // depthwise 3x3 (f32x2), thread = (channel, 2-col group), rolling rows
        {
            int ch = tid & 127, g = tid >> 7;
            const float* wd = (const float*)(smc + ARENA_F * 4 + DWB
                                             + (c & 1) * 4608) + ch * 9;
            uint64_t ww[9];
            #pragma unroll
            for (int t = 0; t < 9; ++t) { float w = wd[t]; ww[t] = pk2(w, w); }
            const float* hb = &sm[OFF_HID + ch * 101 + 2 * g];
            uint64_t Ap[3], Bp[3], Cp[3];
            {
                float a0 = hb[0], a1 = hb[1], a2 = hb[2], a3 = hb[3];
                Ap[0] = pk2(a0, a1); Ap[1] = pk2(a1, a2); Ap[2] = pk2(a2, a3);
                float b0 = hb[10], b1 = hb[11], b2 = hb[12], b3 = hb[13];
                Bp[0] = pk2(b0, b1); Bp[1] = pk2(b1, b2); Bp[2] = pk2(b2, b3);
            }
            float* qrow = &sm[OFF_QKV + (c * 128 + ch) * 65 + 2 * g];
            #pragma unroll
            for (int r = 2; r < 10; ++r) {
                float c0 = hb[r*10+0], c1 = hb[r*10+1], c2 = hb[r*10+2], c3 = hb[r*10+3];
                Cp[0] = pk2(c0, c1); Cp[1] = pk2(c1, c2); Cp[2] = pk2(c2, c3);
                uint64_t s2 = pk2(0.f, 0.f);
                fma2(s2, ww[0], Ap[0]); fma2(s2, ww[1], Ap[1]); fma2(s2, ww[2], Ap[2]);
                fma2(s2, ww[3], Bp[0]); fma2(s2, ww[4], Bp[1]); fma2(s2, ww[5], Bp[2]);
                fma2(s2, ww[6], Cp[0]); fma2(s2, ww[7], Cp[1]); fma2(s2, ww[8], Cp[2]);
                float o0, o1; upk2(o0, o1, s2);
                int yy = r - 2;
                qrow[yy * 8 + 0] = o0; qrow[yy * 8 + 1] = o1;
                Ap[0]=Bp[0]; Ap[1]=Bp[1]; Ap[2]=Bp[2];
                Bp[0]=Cp[0]; Bp[1]=Cp[1]; Bp[2]=Cp[2];
            }
        }
        if (c < 2) __syncthreads();   // protects HID vs next HMMA; skip at c==2
    }

    // ---- phase 2: RMS factors for q and k (warp -> 4 pixels) ----
    #pragma unroll
    for (int pi = 0; pi < 4; ++pi) {
        int pix = warp * 4 + pi;
        float sq = 0.f, sk = 0.f;
        #pragma unroll
        for (int r = 0; r < 4; ++r) {
            int cc = lane + r * 32;
            float qv = sm[OFF_QKV + cc * 65 + pix];
            float kv = sm[OFF_QKV + (128 + cc) * 65 + pix];
            sq = fmaf(qv, qv, sq);
            sk = fmaf(kv, kv, sk);
        }
        #pragma unroll
        for (int off = 16; off; off >>= 1) {
            sq += __shfl_xor_sync(0xffffffffu, sq, off);
            sk += __shfl_xor_sync(0xffffffffu, sk, off);
        }
        if (lane == 0) {
            sm[OFF_RQ + pix] = rsqrtf(sq * (1.f / 128.f) + EPSF);
            sm[OFF_RK + pix] = rsqrtf(sk * (1.f / 128.f) + EPSF);
        }
    }
    __syncthreads();

    // ---- phase 3: RMSNorm scale + 2D RoPE (table-driven) ----
    for (int idx = tid; idx < 64 * 64; idx += 512) {
        int m = idx >> 6, pix = idx & 63;
        int flag = (m >> 5), mm = m & 31;
        int d = flag ? (pix & 7) : (pix >> 3);
        float cs = sm[OFF_SC + flag * 256 + mm * 8 + d];
        float sn = sm[OFF_SC + 512 + flag * 256 + mm * 8 + d];
        int c0 = 2 * m;
        float rqp = sm[OFF_RQ + pix], rkp = sm[OFF_RK + pix];
        float gq0 = sm[OFF_G + 128 + c0], gq1 = sm[OFF_G + 129 + c0];
        float gk0 = sm[OFF_G + 256 + c0], gk1 = sm[OFF_G + 257 + c0];

        float q0 = sm[OFF_QKV + c0 * 65 + pix]       * rqp * gq0;
        float q1 = sm[OFF_QKV + (c0 + 1) * 65 + pix] * rqp * gq1;
        sm[OFF_QKV + c0 * 65 + pix]       = q0 * cs - q1 * sn;
        sm[OFF_QKV + (c0 + 1) * 65 + pix] = q1 * cs + q0 * sn;

        float k0 = sm[OFF_QKV + (128 + c0) * 65 + pix] * rkp * gk0;
        float k1 = sm[OFF_QKV + (129 + c0) * 65 + pix] * rkp * gk1;
        sm[OFF_QKV + (128 + c0) * 65 + pix] = k0 * cs - k1 * sn;
        sm[OFF_QKV + (129 + c0) * 65 + pix] = k1 * cs + k0 * sn;
    }
    __syncthreads();

    // ---- phase 4: circ conv, f32x2 parity-split ----
    {
        const int cc = tid & 127;
        const int A0 = ((tid >> 7) & 1) * 4;
        const int P  = tid >> 8;
        const float* qb = &sm[OFF_QKV + cc * 65];
        const float* kb = &sm[OFF_QKV + (128 + cc) * 65];
        float v32[32];
        if (P == 0) circ_par<0>(qb, kb, A0, v32);
        else        circ_par<1>(qb, kb, A0, v32);

        float* scratch = (float*)(smc + ARENA_F * 4 + CBH);   // 256 x 33 floats
        int s = tid & 255;
        if (P == 1) {
            #pragma unroll
            for (int t = 0; t < 32; ++t) scratch[s * 33 + t] = v32[t];
        }
        __syncthreads();
        if (P == 0) {
            #pragma unroll
            for (int t = 0; t < 32; ++t) {
                float tot = v32[t] + scratch[s * 33 + t];
                sm[OFF_CORR + cc * 65 + (A0 + (t >> 3)) * 8 + (t & 7)] = tot;
            }
        }
    }
    __syncthreads();

    // ---- proj A-frags via LDG (latency hidden under phases 5+6) ----
    uint4 pfh[8], pfl[8];
    #pragma unroll
    for (int ks = 0; ks < 8; ++ks) {
        int slot = (mg * 8 + ks) * 32 + lane;
        pfh[ks] = *(const uint4*)&g_pfh[slot * 4];
        pfl[ks] = *(const uint4*)&g_pfl[slot * 4];
    }

    // ---- phase 5: corr RMS factor (warp -> 4 pixels) ----
    #pragma unroll
    for (int pi = 0; pi < 4; ++pi) {
        int pix = warp * 4 + pi;
        float sc = 0.f;
        #pragma unroll
        for (int r = 0; r < 4; ++r) {
            float cv = sm[OFF_CORR + (lane + r * 32) * 65 + pix];
            sc = fmaf(cv, cv, sc);
        }
        #pragma unroll
        for (int off = 16; off; off >>= 1)
            sc += __shfl_xor_sync(0xffffffffu, sc, off);
        if (lane == 0)
            sm[OFF_RN + pix] = rsqrtf(sc * (1.f / 128.f) + EPSF);
    }
    __syncthreads();

    // ---- phase 6: (v * g_norm * rn * corr) -> bf16 hi/lo B tiles [pix][k] ----
    for (int idx = tid; idx < 64 * 64; idx += 512) {
        int pix = idx >> 6, kp = idx & 63;
        int k0 = 2 * kp;
        float rnp = sm[OFF_RN + pix];
        float c0v = sm[OFF_CORR + k0 * 65 + pix];
        float c1v = sm[OFF_CORR + (k0 + 1) * 65 + pix];
        float v0  = sm[OFF_QKV + (256 + k0) * 65 + pix];
        float v1  = sm[OFF_QKV + (257 + k0) * 65 + pix];
        float w0 = v0 * c0v * rnp * sm[OFF_G + k0];
        float w1 = v1 * c1v * rnp * sm[OFF_G + k0 + 1];
        uint32_t lp, hp = pack_hi_lo(w0, w1, lp);
        *(uint32_t*)(smc + ARENA_F * 4 + CBH + pix * 272 + kp * 4) = hp;
        *(uint32_t*)(smc + ARENA_F * 4 + CBL + pix * 272 + kp * 4) = lp;
    }
    __syncthreads();

    // ---- phase 7: projection HMMA on 16 warps (A from regs) ----
    {
        const int nh = warp >> 2;
        float* ob = out + (size_t)b * 64 * HH * WW;
        #pragma unroll
        for (int t = 0; t < 2; ++t) {
            int nt = nh * 2 + t;
            float acc[4] = {};
            // B hi+lo via ONE ldsm4: lanes 0-15 hi tile, 16-31 lo tile
            const uint32_t bB = arena + CBH + (lane >> 4) * (CBL - CBH)
                                + (nt * 8 + (lane & 7)) * 272
                                + ((lane >> 3) & 1) * 16;
            #pragma unroll
            for (int ks = 0; ks < 8; ++ks) {
                uint32_t bf[4];
                ldsm4(bf, bB + ks * 32);
                mma16816v(acc, pfh[ks], bf[0], bf[1]);   // hi*hi
                mma16816v(acc, pfh[ks], bf[2], bf[3]);   // hi*lo
                mma16816v(acc, pfl[ks], bf[0], bf[1]);   // lo*hi
            }
            int o = mg * 16 + (lane >> 2);
            int gy = gy0 + nt;
            int gxp = gx0 + 2 * (lane & 3);
            *(float2*)(ob + (size_t)o * (HH * WW) + gy * WW + gxp)
                = make_float2(acc[0], acc[1]);
            *(float2*)(ob + (size_t)(o + 8) * (HH * WW) + gy * WW + gxp)
                = make_float2(acc[2], acc[3]);
        }
    }
}

extern "C" void kernel_launch(void* const* d_in, const int* in_sizes, int n_in,
                              void* d_out, int out_size)
{
    (void)in_sizes; (void)n_in; (void)out_size;
    const float* x        = (const float*)d_in[0];
    const float* w_hidden = (const float*)d_in[1];
    const float* w_dw     = (const float*)d_in[2];
    const float* w_proj   = (const float*)d_in[3];
    const float* g_norm   = (const float*)d_in[4];
    const float* g_qnorm  = (const float*)d_in[5];
    const float* g_knorm  = (const float*)d_in[6];
    float* out = (float*)d_out;

    prep_weights<<<16, 256>>>(w_hidden, w_proj);

    cudaFuncSetAttribute(fsas_fused_kernel,
                         cudaFuncAttributeMaxDynamicSharedMemorySize, SMEM_BYTES);
    dim3 grid(WW / 8, HH / 8, 4);
    fsas_fused_kernel<<<grid, 512, SMEM_BYTES>>>(
        x, w_dw, g_norm, g_qnorm, g_knorm, out);
}